// round 16
// baseline (speedup 1.0000x reference)
#include <cuda_runtime.h>
#include <cstdint>
#include <cstddef>

// B=4, Lq=1024, Lk=2048, D=1024, H=16, Dh=64, MAX_POS=2048
#define BATCH 4
#define LQ 1024
#define LK 2048
#define DMODEL 1024
#define NHEAD 16
#define DH 64
#define ZTOT (BATCH * NHEAD)   // 64

// ---------------- scratch ----------------
__device__ float gQ [(size_t)ZTOT * LQ * DH];          // [z][l][dh]  (tf32-rounded)
__device__ float gK [(size_t)ZTOT * LK * DH];          // [z][r][dh]  (tf32-rounded)
__device__ float gVt[(size_t)ZTOT * DH * LK];          // [z][dh][r]  (tf32-rounded)
__device__ float gEr[(size_t)4095 * DH];               // tf32-rounded dist_emb

// ---------------- helpers ----------------
__device__ __forceinline__ float tf32r(float x) {
    uint32_t u;
    asm("cvt.rna.tf32.f32 %0, %1;" : "=r"(u) : "f"(x));
    return __uint_as_float(u);
}

__device__ __forceinline__ void mma_tf32(float c[4], const uint32_t a[4], const uint32_t b[2]) {
    asm volatile(
        "mma.sync.aligned.m16n8k8.row.col.f32.tf32.tf32.f32 "
        "{%0,%1,%2,%3}, {%4,%5,%6,%7}, {%8,%9}, {%0,%1,%2,%3};"
        : "+f"(c[0]), "+f"(c[1]), "+f"(c[2]), "+f"(c[3])
        : "r"(a[0]), "r"(a[1]), "r"(a[2]), "r"(a[3]),
          "r"(b[0]), "r"(b[1]));
}

// ============================================================================
// Merged projections + emb rounding, one launch.
// blocks [0,128)   mode0 (Q, M=4096)
// blocks [128,384) mode1 (K, M=8192)
// blocks [384,640) mode2 (V, M=8192)
// blocks [640,768) emb tf32-rounding
// Proj tile 256x128x32, 512 threads, register-prefetch pipeline.
// ============================================================================
#define PR_SMEM_FLOATS (256 * 36 + 128 * 36)    // 13824
#define PR_SMEM_BYTES  (PR_SMEM_FLOATS * 4)     // 55296

__global__ __launch_bounds__(512)
void proj_all(const float* __restrict__ hid, const float* __restrict__ qhid,
              const float* __restrict__ Wq, const float* __restrict__ bq,
              const float* __restrict__ Wk, const float* __restrict__ bk,
              const float* __restrict__ Wv, const float* __restrict__ bv,
              const float* __restrict__ emb)
{
    extern __shared__ float psm[];
    float (*As)[36] = (float(*)[36])psm;            // [256][36]
    float (*Bs)[36] = (float(*)[36])(psm + 9216);   // [128][36]

    int bid = blockIdx.x;

    // ---- emb-rounding blocks ----
    if (bid >= 640) {
        int i = (bid - 640) * 512 + threadIdx.x;     // float4 index
        if (i < 4095 * DH / 4) {
            float4 v = ((const float4*)emb)[i];
            float4 r;
            r.x = tf32r(v.x); r.y = tf32r(v.y); r.z = tf32r(v.z); r.w = tf32r(v.w);
            ((float4*)gEr)[i] = r;
        }
        return;
    }

    int mode;
    const float* A; const float* W; const float* bias;
    if (bid < 128)      { mode = 0; A = qhid; W = Wq; bias = bq; }
    else if (bid < 384) { mode = 1; bid -= 128; A = hid; W = Wk; bias = bk; }
    else                { mode = 2; bid -= 384; A = hid; W = Wv; bias = bv; }
    const int m0 = (bid >> 3) * 256;
    const int n0 = (bid & 7) * 128;

    const int tid  = threadIdx.x;
    const int warp = tid >> 5;
    const int lane = tid & 31;
    const int g = lane >> 2;
    const int t = lane & 3;
    const int wm = (warp & 3) * 64;
    const int wn = (warp >> 2) * 32;

    float acc[4][4][4];
#pragma unroll
    for (int i = 0; i < 4; i++)
#pragma unroll
        for (int j = 0; j < 4; j++)
#pragma unroll
            for (int r = 0; r < 4; r++) acc[i][j][r] = 0.f;

    // ---- prologue: prefetch k0 = 0 ----
    float4 pa[4], pb[2];
#pragma unroll
    for (int q = 0; q < 4; q++) {
        int idx = tid + q * 512;                 // 0..2047
        pa[q] = *(const float4*)&A[(size_t)(m0 + (idx >> 3)) * 1024 + ((idx & 7) << 2)];
    }
#pragma unroll
    for (int q = 0; q < 2; q++) {
        int idx = tid + q * 512;                 // 0..1023
        pb[q] = *(const float4*)&W[(size_t)(n0 + (idx >> 3)) * 1024 + ((idx & 7) << 2)];
    }

    for (int k0 = 0; k0 < 1024; k0 += 32) {
        // ---- store prefetched chunk (with tf32 rounding) ----
#pragma unroll
        for (int q = 0; q < 4; q++) {
            int idx = tid + q * 512;
            int row = idx >> 3, kc = (idx & 7) << 2;
            As[row][kc + 0] = tf32r(pa[q].x); As[row][kc + 1] = tf32r(pa[q].y);
            As[row][kc + 2] = tf32r(pa[q].z); As[row][kc + 3] = tf32r(pa[q].w);
        }
#pragma unroll
        for (int q = 0; q < 2; q++) {
            int idx = tid + q * 512;
            int row = idx >> 3, kc = (idx & 7) << 2;
            Bs[row][kc + 0] = tf32r(pb[q].x); Bs[row][kc + 1] = tf32r(pb[q].y);
            Bs[row][kc + 2] = tf32r(pb[q].z); Bs[row][kc + 3] = tf32r(pb[q].w);
        }
        __syncthreads();

        // ---- issue next chunk's loads (overlap with MMA below) ----
        if (k0 + 32 < 1024) {
            const int kn = k0 + 32;
#pragma unroll
            for (int q = 0; q < 4; q++) {
                int idx = tid + q * 512;
                pa[q] = *(const float4*)&A[(size_t)(m0 + (idx >> 3)) * 1024 + kn + ((idx & 7) << 2)];
            }
#pragma unroll
            for (int q = 0; q < 2; q++) {
                int idx = tid + q * 512;
                pb[q] = *(const float4*)&W[(size_t)(n0 + (idx >> 3)) * 1024 + kn + ((idx & 7) << 2)];
            }
        }

        // ---- MMA phase ----
#pragma unroll
        for (int k8 = 0; k8 < 4; k8++) {
            const int c0 = k8 * 8 + t, c1 = c0 + 4;
            uint32_t af[4][4], bf[4][2];
#pragma unroll
            for (int mt = 0; mt < 4; mt++) {
                int r0 = wm + mt * 16 + g;
                af[mt][0] = __float_as_uint(As[r0][c0]);
                af[mt][1] = __float_as_uint(As[r0 + 8][c0]);
                af[mt][2] = __float_as_uint(As[r0][c1]);
                af[mt][3] = __float_as_uint(As[r0 + 8][c1]);
            }
#pragma unroll
            for (int nt = 0; nt < 4; nt++) {
                int nr = wn + nt * 8 + g;
                bf[nt][0] = __float_as_uint(Bs[nr][c0]);
                bf[nt][1] = __float_as_uint(Bs[nr][c1]);
            }
#pragma unroll
            for (int mt = 0; mt < 4; mt++)
#pragma unroll
                for (int nt = 0; nt < 4; nt++)
                    mma_tf32(acc[mt][nt], af[mt], bf[nt]);
        }
        __syncthreads();
    }

    // ---- epilogue: bias + tf32 round + scatter per mode ----
#pragma unroll
    for (int mt = 0; mt < 4; mt++) {
#pragma unroll
        for (int nt = 0; nt < 4; nt++) {
#pragma unroll
            for (int half = 0; half < 2; half++) {
                int m = m0 + wm + mt * 16 + g + half * 8;
#pragma unroll
                for (int cc = 0; cc < 2; cc++) {
                    int n = n0 + wn + nt * 8 + t * 2 + cc;
                    float c = tf32r(acc[mt][nt][half * 2 + cc] + bias[n]);
                    int h = n >> 6, dh = n & 63;
                    if (mode == 0) {
                        int b = m >> 10, l = m & 1023;
                        gQ[((((size_t)b * NHEAD + h) * LQ) + l) * DH + dh] = c;
                    } else if (mode == 1) {
                        int b = m >> 11, tt = m & 2047;
                        gK[((((size_t)b * NHEAD + h) * LK) + tt) * DH + dh] = c;
                    } else {
                        int b = m >> 11, tt = m & 2047;
                        gVt[((((size_t)b * NHEAD + h) * DH) + dh) * LK + tt] = c;
                    }
                }
            }
        }
    }
}

// ============================================================================
// Fused flash attention (scores + softmax + PV), tensor-core tf32 (mma.sync).
// R14 config + K-tile register prefetch: next tile's K is loaded into
// registers during the PV phase (Oacc-only pressure window) and stored to
// smem at the next loop top, hiding the ~600-cycle K load latency.
// ============================================================================
#define FL_QS   0
#define FL_KS   8704
#define FL_EV   17408
#define FL_PE   34816
#define FL_RS   55808
#define FL_TOT  56320
#define FL_SMEM_BYTES (FL_TOT * 4)   // 225,280 bytes

__global__ __launch_bounds__(512)
void flash_tc(const float* __restrict__ mask, float* __restrict__ out)
{
    extern __shared__ float sm[];
    float (*Qs)[68]   = (float(*)[68]) (sm + FL_QS);
    float (*Ks)[68]   = (float(*)[68]) (sm + FL_KS);
    float (*Vs)[132]  = (float(*)[132])(sm + FL_KS);   // aliases Ks
    float (*Es)[68]   = (float(*)[68]) (sm + FL_EV);   // ring, slot = j & 255
    float (*Ocmb)[68] = (float(*)[68]) (sm + FL_EV);   // epilogue only
    float (*PE)[164]  = (float(*)[164])(sm + FL_PE);
    float (*Ps)[132]  = (float(*)[132])(sm + FL_PE);
    float* rsum       = sm + FL_RS;                    // [4][128]

    const int z  = blockIdx.y;
    const int m0 = blockIdx.x * 128;

    const float* Aq = gQ + (size_t)z * LQ * DH;
    const float* Bk = gK + (size_t)z * LK * DH;
    const float* Vt = gVt + (size_t)z * DH * LK;

    const int tid  = threadIdx.x;
    const int warp = tid >> 5;
    const int lane = tid & 31;
    const int g = lane >> 2;
    const int t = lane & 3;
    const int wm    = (warp & 3) * 32;
    const int wnidx = warp >> 2;          // 0..3
    const int wn    = wnidx * 32;
    const int pv_kh = (warp >> 2) & 1;    // k half
    const int pv_ng = (warp >> 3) & 1;    // n group (32 cols)

    // K-staging thread coords (fixed per thread)
    const int krow = tid >> 2;            // 0..127
    const int kc4  = (tid & 3) << 2;      // 0,4,8,12 -> float4 col base*?  (16 cols => 4 float4)

    // ---- stage Q once (pre-rounded; pure float4 copy) ----
#pragma unroll
    for (int qq = 0; qq < 4; qq++) {
        int idx = tid + qq * 512;            // 0..2047
        int row = idx >> 4;
        int c4  = (idx & 15) << 2;
        *(float4*)&Qs[row][c4] = *(const float4*)&Aq[(size_t)(m0 + row) * DH + c4];
    }
    rsum[tid] = 0.f;

    float Oacc[2][4][4];
#pragma unroll
    for (int i = 0; i < 2; i++)
#pragma unroll
        for (int j = 0; j < 4; j++)
#pragma unroll
            for (int r = 0; r < 4; r++) Oacc[i][j][r] = 0.f;

    const float* mbase = mask + (size_t)(z >> 4) * LK;

    // ---- prologue: prefetch K tile 0 into registers ----
    // Each thread owns one row (krow) x 16 consecutive floats (4 float4 at
    // columns 16*(tid&3).. wait: use 4 chunks of idx pattern like staging.
    float4 pk[4];
#pragma unroll
    for (int qq = 0; qq < 4; qq++) {
        int idx = tid + qq * 512;            // 0..2047
        int row = idx >> 4;
        int c4  = (idx & 15) << 2;
        pk[qq] = *(const float4*)&Bk[(size_t)row * DH + c4];
    }

    for (int n0 = 0; n0 < LK; n0 += 128) {
        __syncthreads();   // previous PV reads of Ps/Vs done before restaging

        const int jlo = m0 - n0 + 1920;      // in [0, 2816]; -128 per tile

        // ---- store prefetched K tile ----
#pragma unroll
        for (int qq = 0; qq < 4; qq++) {
            int idx = tid + qq * 512;        // 0..2047
            int row = idx >> 4;              // 0..127
            int c4  = (idx & 15) << 2;
            *(float4*)&Ks[row][c4] = pk[qq];
        }
        // ---- stage E ring: full window first tile, 128 new rows after ----
        if (n0 == 0) {
#pragma unroll
            for (int qq = 0; qq < 8; qq++) {
                int idx = tid + qq * 512;    // 0..4095
                int row = idx >> 4;          // 0..255
                int c4  = (idx & 15) << 2;
                int j   = jlo + row;
                *(float4*)&Es[j & 255][c4] = *(const float4*)&gEr[(size_t)j * DH + c4];
            }
        } else {
#pragma unroll
            for (int qq = 0; qq < 4; qq++) {
                int idx = tid + qq * 512;    // 0..2047
                int row = idx >> 4;          // 0..127 (new low rows)
                int c4  = (idx & 15) << 2;
                int j   = jlo + row;
                *(float4*)&Es[j & 255][c4] = *(const float4*)&gEr[(size_t)j * DH + c4];
            }
        }
        __syncthreads();

        float acc[2][4][4];
#pragma unroll
        for (int i = 0; i < 2; i++)
#pragma unroll
            for (int j = 0; j < 4; j++)
#pragma unroll
                for (int r = 0; r < 4; r++) acc[i][j][r] = 0.f;

        // ---- S = Q @ K^T ----
#pragma unroll
        for (int k8 = 0; k8 < 8; k8++) {
            const int c0 = k8 * 8 + t, c1 = c0 + 4;
            uint32_t af[2][4], bf[4][2];
#pragma unroll
            for (int mt = 0; mt < 2; mt++) {
                int r0 = wm + mt * 16 + g;
                af[mt][0] = __float_as_uint(Qs[r0][c0]);
                af[mt][1] = __float_as_uint(Qs[r0 + 8][c0]);
                af[mt][2] = __float_as_uint(Qs[r0][c1]);
                af[mt][3] = __float_as_uint(Qs[r0 + 8][c1]);
            }
#pragma unroll
            for (int nt = 0; nt < 4; nt++) {
                int nr = wn + nt * 8 + g;
                bf[nt][0] = __float_as_uint(Ks[nr][c0]);
                bf[nt][1] = __float_as_uint(Ks[nr][c1]);
            }
#pragma unroll
            for (int mt = 0; mt < 2; mt++)
#pragma unroll
                for (int nt = 0; nt < 4; nt++)
                    mma_tf32(acc[mt][nt], af[mt], bf[nt]);
        }

        // ---- banded positional passes (src 0 = Q-side, src 1 = K-side) ----
#pragma unroll 1
        for (int src = 0; src < 2; src++) {
            const float (*Src)[68] = (src == 0) ? Qs : Ks;
            const int ebase  = (src == 0) ? wm : (96 - wm);
            const int estart = jlo + ebase + wnidx * 40;   // ABSOLUTE e start

            float pacc[2][5][4];
#pragma unroll
            for (int i = 0; i < 2; i++)
#pragma unroll
                for (int j = 0; j < 5; j++)
#pragma unroll
                    for (int r = 0; r < 4; r++) pacc[i][j][r] = 0.f;

#pragma unroll
            for (int k8 = 0; k8 < 8; k8++) {
                const int c0 = k8 * 8 + t, c1 = c0 + 4;
                uint32_t af[2][4], bf[5][2];
#pragma unroll
                for (int mt = 0; mt < 2; mt++) {
                    int r0 = wm + mt * 16 + g;
                    af[mt][0] = __float_as_uint(Src[r0][c0]);
                    af[mt][1] = __float_as_uint(Src[r0 + 8][c0]);
                    af[mt][2] = __float_as_uint(Src[r0][c1]);
                    af[mt][3] = __float_as_uint(Src[r0 + 8][c1]);
                }
#pragma unroll
                for (int nt = 0; nt < 5; nt++) {
                    int er = (estart + nt * 8 + g) & 255;  // ring slot
                    bf[nt][0] = __float_as_uint(Es[er][c0]);
                    bf[nt][1] = __float_as_uint(Es[er][c1]);
                }
#pragma unroll
                for (int mt = 0; mt < 2; mt++)
#pragma unroll
                    for (int nt = 0; nt < 5; nt++)
                        mma_tf32(pacc[mt][nt], af[mt], bf[nt]);
            }

            // store band fragment (float2)
#pragma unroll
            for (int mt = 0; mt < 2; mt++)
#pragma unroll
                for (int half = 0; half < 2; half++) {
                    int r = wm + mt * 16 + g + half * 8;
#pragma unroll
                    for (int nt = 0; nt < 5; nt++) {
                        float2 v2;
                        v2.x = pacc[mt][nt][half * 2 + 0];
                        v2.y = pacc[mt][nt][half * 2 + 1];
                        *(float2*)&PE[r][wnidx * 40 + nt * 8 + t * 2] = v2;
                    }
                }
            __syncthreads();

            // predicate-free diagonal gather
#pragma unroll
            for (int mt = 0; mt < 2; mt++)
#pragma unroll
                for (int half = 0; half < 2; half++) {
                    const int i = wm + mt * 16 + g + half * 8;
#pragma unroll
                    for (int nt = 0; nt < 4; nt++)
#pragma unroll
                        for (int cc = 0; cc < 2; cc++) {
                            const int jj = wn + nt * 8 + t * 2 + cc;
                            if (src == 0)
                                acc[mt][nt][half * 2 + cc] += PE[i][(i & 31) + 127 - jj];
                            else
                                acc[mt][nt][half * 2 + cc] += PE[jj][i - (jj & 31) + 31];
                        }
                }
            __syncthreads();
        }

        // ---- exp + row sums + stash P (tf32) into Ps ----
        {
            float rpart[4] = {0.f, 0.f, 0.f, 0.f};
#pragma unroll
            for (int mt = 0; mt < 2; mt++)
#pragma unroll
                for (int half = 0; half < 2; half++) {
                    const int r = wm + mt * 16 + g + half * 8;
#pragma unroll
                    for (int nt = 0; nt < 4; nt++) {
                        const int nloc = wn + nt * 8 + t * 2;
                        float p0 = __expf(acc[mt][nt][half * 2 + 0] * 0.125f
                                          + mbase[n0 + nloc]);
                        float p1 = __expf(acc[mt][nt][half * 2 + 1] * 0.125f
                                          + mbase[n0 + nloc + 1]);
                        rpart[mt * 2 + half] += p0 + p1;
                        float2 v2; v2.x = tf32r(p0); v2.y = tf32r(p1);
                        *(float2*)&Ps[r][nloc] = v2;
                    }
                }
#pragma unroll
            for (int i = 0; i < 4; i++) {
                rpart[i] += __shfl_xor_sync(0xffffffffu, rpart[i], 1);
                rpart[i] += __shfl_xor_sync(0xffffffffu, rpart[i], 2);
            }
            if (t == 0) {
#pragma unroll
                for (int i = 0; i < 4; i++) {
                    const int r = wm + (i >> 1) * 16 + g + (i & 1) * 8;
                    rsum[wnidx * 128 + r] += rpart[i];
                }
            }
        }

        // ---- stage V tile into Ks region (K reads all done) ----
#pragma unroll
        for (int qq = 0; qq < 4; qq++) {
            int idx = tid + qq * 512;        // 0..2047 float4 slots
            int row = idx >> 5;              // 0..63 (dh)
            int c4  = (idx & 31) << 2;       // 0..124
            *(float4*)&Vs[row][c4] = *(const float4*)&Vt[(size_t)row * LK + n0 + c4];
        }
        __syncthreads();

        // ---- prefetch NEXT K tile into registers (overlaps PV MMAs) ----
        if (n0 + 128 < LK) {
            const int nn = n0 + 128;
#pragma unroll
            for (int qq = 0; qq < 4; qq++) {
                int idx = tid + qq * 512;
                int row = idx >> 4;
                int c4  = (idx & 15) << 2;
                pk[qq] = *(const float4*)&Bk[(size_t)(nn + row) * DH + c4];
            }
        }

        // ---- O += P @ V^T  (warps: 4m x 2n x 2k-split) ----
#pragma unroll
        for (int k8 = 0; k8 < 8; k8++) {
            const int c0 = pv_kh * 64 + k8 * 8 + t, c1 = c0 + 4;
            uint32_t af[2][4], bf[4][2];
#pragma unroll
            for (int mt = 0; mt < 2; mt++) {
                int r0 = wm + mt * 16 + g;
                af[mt][0] = __float_as_uint(Ps[r0][c0]);
                af[mt][1] = __float_as_uint(Ps[r0 + 8][c0]);
                af[mt][2] = __float_as_uint(Ps[r0][c1]);
                af[mt][3] = __float_as_uint(Ps[r0 + 8][c1]);
            }
#pragma unroll
            for (int nt = 0; nt < 4; nt++) {
                int nr = pv_ng * 32 + nt * 8 + g;
                bf[nt][0] = __float_as_uint(Vs[nr][c0]);
                bf[nt][1] = __float_as_uint(Vs[nr][c1]);
            }
#pragma unroll
            for (int mt = 0; mt < 2; mt++)
#pragma unroll
                for (int nt = 0; nt < 4; nt++)
                    mma_tf32(Oacc[mt][nt], af[mt], bf[nt]);
        }
    }

    // ---- epilogue: combine k-split halves, normalize, write out ----
    __syncthreads();
    if (tid < 128) {
        float s = rsum[tid] + rsum[128 + tid] + rsum[256 + tid] + rsum[384 + tid];
        rsum[tid] = 1.0f / s;
    }
    if (pv_kh == 1) {
#pragma unroll
        for (int mt = 0; mt < 2; mt++)
#pragma unroll
            for (int half = 0; half < 2; half++) {
                const int r = wm + mt * 16 + g + half * 8;
#pragma unroll
                for (int nt = 0; nt < 4; nt++) {
                    float2 v2;
                    v2.x = Oacc[mt][nt][half * 2 + 0];
                    v2.y = Oacc[mt][nt][half * 2 + 1];
                    *(float2*)&Ocmb[r][pv_ng * 32 + nt * 8 + t * 2] = v2;
                }
            }
    }
    __syncthreads();
    if (pv_kh == 0) {
        const int b = z >> 4, h = z & 15;
#pragma unroll
        for (int mt = 0; mt < 2; mt++)
#pragma unroll
            for (int half = 0; half < 2; half++) {
                const int r = wm + mt * 16 + g + half * 8;
                const float inv = rsum[r];
#pragma unroll
                for (int nt = 0; nt < 4; nt++) {
                    const int ncol = pv_ng * 32 + nt * 8 + t * 2;
                    float2 o;
                    o.x = (Oacc[mt][nt][half * 2 + 0] + Ocmb[r][ncol + 0]) * inv;
                    o.y = (Oacc[mt][nt][half * 2 + 1] + Ocmb[r][ncol + 1]) * inv;
                    *(float2*)&out[((size_t)b * LQ + m0 + r) * DMODEL + h * DH + ncol] = o;
                }
            }
    }
}

// ---------------- host ----------------
extern "C" void kernel_launch(void* const* d_in, const int* in_sizes, int n_in,
                              void* d_out, int out_size)
{
    (void)in_sizes; (void)n_in; (void)out_size;
    const float* hid  = (const float*)d_in[0];   // [4,2048,1024]
    const float* qhid = (const float*)d_in[1];   // [4,1024,1024]
    const float* mask = (const float*)d_in[2];   // [4,1,1,2048]
    const float* Wq   = (const float*)d_in[3];
    const float* bq   = (const float*)d_in[4];
    const float* Wk   = (const float*)d_in[5];
    const float* bk   = (const float*)d_in[6];
    const float* Wv   = (const float*)d_in[7];
    const float* bv   = (const float*)d_in[8];
    const float* emb  = (const float*)d_in[9];   // [4095,64]
    float* out = (float*)d_out;                  // [4,1024,1024]

    static bool attr_set = false;
    if (!attr_set) {
        cudaFuncSetAttribute(flash_tc,
                             cudaFuncAttributeMaxDynamicSharedMemorySize,
                             FL_SMEM_BYTES);
        cudaFuncSetAttribute(proj_all,
                             cudaFuncAttributeMaxDynamicSharedMemorySize,
                             PR_SMEM_BYTES);
        attr_set = true;
    }

    proj_all<<<768, 512, PR_SMEM_BYTES>>>(hid, qhid, Wq, bq, Wk, bk, Wv, bv, emb);

    flash_tc<<<dim3(LQ / 128, ZTOT), 512, FL_SMEM_BYTES>>>(mask, out);
}

// round 17
// speedup vs baseline: 1.0261x; 1.0261x over previous
#include <cuda_runtime.h>
#include <cstdint>
#include <cstddef>

// B=4, Lq=1024, Lk=2048, D=1024, H=16, Dh=64, MAX_POS=2048
#define BATCH 4
#define LQ 1024
#define LK 2048
#define DMODEL 1024
#define NHEAD 16
#define DH 64
#define ZTOT (BATCH * NHEAD)   // 64

// ---------------- scratch ----------------
__device__ float gQ [(size_t)ZTOT * LQ * DH];          // [z][l][dh]  (tf32-rounded)
__device__ float gK [(size_t)ZTOT * LK * DH];          // [z][r][dh]  (tf32-rounded)
__device__ float gVt[(size_t)ZTOT * DH * LK];          // [z][dh][r]  (tf32-rounded)
__device__ float gEr[(size_t)4095 * DH];               // tf32-rounded dist_emb

// ---------------- helpers ----------------
__device__ __forceinline__ float tf32r(float x) {
    uint32_t u;
    asm("cvt.rna.tf32.f32 %0, %1;" : "=r"(u) : "f"(x));
    return __uint_as_float(u);
}

__device__ __forceinline__ void mma_tf32(float c[4], const uint32_t a[4], const uint32_t b[2]) {
    asm volatile(
        "mma.sync.aligned.m16n8k8.row.col.f32.tf32.tf32.f32 "
        "{%0,%1,%2,%3}, {%4,%5,%6,%7}, {%8,%9}, {%0,%1,%2,%3};"
        : "+f"(c[0]), "+f"(c[1]), "+f"(c[2]), "+f"(c[3])
        : "r"(a[0]), "r"(a[1]), "r"(a[2]), "r"(a[3]),
          "r"(b[0]), "r"(b[1]));
}

// ============================================================================
// Merged projections + emb rounding, one launch.
// blocks [0,128)   mode0 (Q, M=4096)
// blocks [128,384) mode1 (K, M=8192)
// blocks [384,640) mode2 (V, M=8192)
// blocks [640,768) emb tf32-rounding
// Proj tile 256x128x32, 512 threads (16 warps, 4m x 4n, warp tile 64x32),
// register-prefetch pipeline.
// ============================================================================
#define PR_SMEM_FLOATS (256 * 36 + 128 * 36)    // 13824
#define PR_SMEM_BYTES  (PR_SMEM_FLOATS * 4)     // 55296

__global__ __launch_bounds__(512)
void proj_all(const float* __restrict__ hid, const float* __restrict__ qhid,
              const float* __restrict__ Wq, const float* __restrict__ bq,
              const float* __restrict__ Wk, const float* __restrict__ bk,
              const float* __restrict__ Wv, const float* __restrict__ bv,
              const float* __restrict__ emb)
{
    extern __shared__ float psm[];
    float (*As)[36] = (float(*)[36])psm;            // [256][36]
    float (*Bs)[36] = (float(*)[36])(psm + 9216);   // [128][36]

    int bid = blockIdx.x;

    // ---- emb-rounding blocks ----
    if (bid >= 640) {
        int i = (bid - 640) * 512 + threadIdx.x;     // float4 index
        if (i < 4095 * DH / 4) {
            float4 v = ((const float4*)emb)[i];
            float4 r;
            r.x = tf32r(v.x); r.y = tf32r(v.y); r.z = tf32r(v.z); r.w = tf32r(v.w);
            ((float4*)gEr)[i] = r;
        }
        return;
    }

    int mode;
    const float* A; const float* W; const float* bias;
    if (bid < 128)      { mode = 0; A = qhid; W = Wq; bias = bq; }
    else if (bid < 384) { mode = 1; bid -= 128; A = hid; W = Wk; bias = bk; }
    else                { mode = 2; bid -= 384; A = hid; W = Wv; bias = bv; }
    const int m0 = (bid >> 3) * 256;
    const int n0 = (bid & 7) * 128;

    const int tid  = threadIdx.x;
    const int warp = tid >> 5;
    const int lane = tid & 31;
    const int g = lane >> 2;
    const int t = lane & 3;
    const int wm = (warp & 3) * 64;
    const int wn = (warp >> 2) * 32;

    float acc[4][4][4];
#pragma unroll
    for (int i = 0; i < 4; i++)
#pragma unroll
        for (int j = 0; j < 4; j++)
#pragma unroll
            for (int r = 0; r < 4; r++) acc[i][j][r] = 0.f;

    // ---- prologue: prefetch k0 = 0 ----
    float4 pa[4], pb[2];
#pragma unroll
    for (int q = 0; q < 4; q++) {
        int idx = tid + q * 512;                 // 0..2047
        pa[q] = *(const float4*)&A[(size_t)(m0 + (idx >> 3)) * 1024 + ((idx & 7) << 2)];
    }
#pragma unroll
    for (int q = 0; q < 2; q++) {
        int idx = tid + q * 512;                 // 0..1023
        pb[q] = *(const float4*)&W[(size_t)(n0 + (idx >> 3)) * 1024 + ((idx & 7) << 2)];
    }

    for (int k0 = 0; k0 < 1024; k0 += 32) {
        // ---- store prefetched chunk (with tf32 rounding) ----
#pragma unroll
        for (int q = 0; q < 4; q++) {
            int idx = tid + q * 512;
            int row = idx >> 3, kc = (idx & 7) << 2;
            As[row][kc + 0] = tf32r(pa[q].x); As[row][kc + 1] = tf32r(pa[q].y);
            As[row][kc + 2] = tf32r(pa[q].z); As[row][kc + 3] = tf32r(pa[q].w);
        }
#pragma unroll
        for (int q = 0; q < 2; q++) {
            int idx = tid + q * 512;
            int row = idx >> 3, kc = (idx & 7) << 2;
            Bs[row][kc + 0] = tf32r(pb[q].x); Bs[row][kc + 1] = tf32r(pb[q].y);
            Bs[row][kc + 2] = tf32r(pb[q].z); Bs[row][kc + 3] = tf32r(pb[q].w);
        }
        __syncthreads();

        // ---- issue next chunk's loads (overlap with MMA below) ----
        if (k0 + 32 < 1024) {
            const int kn = k0 + 32;
#pragma unroll
            for (int q = 0; q < 4; q++) {
                int idx = tid + q * 512;
                pa[q] = *(const float4*)&A[(size_t)(m0 + (idx >> 3)) * 1024 + kn + ((idx & 7) << 2)];
            }
#pragma unroll
            for (int q = 0; q < 2; q++) {
                int idx = tid + q * 512;
                pb[q] = *(const float4*)&W[(size_t)(n0 + (idx >> 3)) * 1024 + kn + ((idx & 7) << 2)];
            }
        }

        // ---- MMA phase ----
#pragma unroll
        for (int k8 = 0; k8 < 4; k8++) {
            const int c0 = k8 * 8 + t, c1 = c0 + 4;
            uint32_t af[4][4], bf[4][2];
#pragma unroll
            for (int mt = 0; mt < 4; mt++) {
                int r0 = wm + mt * 16 + g;
                af[mt][0] = __float_as_uint(As[r0][c0]);
                af[mt][1] = __float_as_uint(As[r0 + 8][c0]);
                af[mt][2] = __float_as_uint(As[r0][c1]);
                af[mt][3] = __float_as_uint(As[r0 + 8][c1]);
            }
#pragma unroll
            for (int nt = 0; nt < 4; nt++) {
                int nr = wn + nt * 8 + g;
                bf[nt][0] = __float_as_uint(Bs[nr][c0]);
                bf[nt][1] = __float_as_uint(Bs[nr][c1]);
            }
#pragma unroll
            for (int mt = 0; mt < 4; mt++)
#pragma unroll
                for (int nt = 0; nt < 4; nt++)
                    mma_tf32(acc[mt][nt], af[mt], bf[nt]);
        }
        __syncthreads();
    }

    // ---- epilogue: bias + tf32 round + scatter per mode ----
#pragma unroll
    for (int mt = 0; mt < 4; mt++) {
#pragma unroll
        for (int nt = 0; nt < 4; nt++) {
#pragma unroll
            for (int half = 0; half < 2; half++) {
                int m = m0 + wm + mt * 16 + g + half * 8;
#pragma unroll
                for (int cc = 0; cc < 2; cc++) {
                    int n = n0 + wn + nt * 8 + t * 2 + cc;
                    float c = tf32r(acc[mt][nt][half * 2 + cc] + bias[n]);
                    int h = n >> 6, dh = n & 63;
                    if (mode == 0) {
                        int b = m >> 10, l = m & 1023;
                        gQ[((((size_t)b * NHEAD + h) * LQ) + l) * DH + dh] = c;
                    } else if (mode == 1) {
                        int b = m >> 11, tt = m & 2047;
                        gK[((((size_t)b * NHEAD + h) * LK) + tt) * DH + dh] = c;
                    } else {
                        int b = m >> 11, tt = m & 2047;
                        gVt[((((size_t)b * NHEAD + h) * DH) + dh) * LK + tt] = c;
                    }
                }
            }
        }
    }
}

// ============================================================================
// Fused flash attention (scores + softmax + PV), tensor-core tf32 (mma.sync).
// Best-measured configuration (R11/R14): full-barrier split passes, E ring,
// Vs aliasing Ks, plain float4 staging.
// ============================================================================
#define FL_QS   0
#define FL_KS   8704
#define FL_EV   17408
#define FL_PE   34816
#define FL_RS   55808
#define FL_TOT  56320
#define FL_SMEM_BYTES (FL_TOT * 4)   // 225,280 bytes

__global__ __launch_bounds__(512)
void flash_tc(const float* __restrict__ mask, float* __restrict__ out)
{
    extern __shared__ float sm[];
    float (*Qs)[68]   = (float(*)[68]) (sm + FL_QS);
    float (*Ks)[68]   = (float(*)[68]) (sm + FL_KS);
    float (*Vs)[132]  = (float(*)[132])(sm + FL_KS);   // aliases Ks
    float (*Es)[68]   = (float(*)[68]) (sm + FL_EV);   // ring, slot = j & 255
    float (*Ocmb)[68] = (float(*)[68]) (sm + FL_EV);   // epilogue only
    float (*PE)[164]  = (float(*)[164])(sm + FL_PE);
    float (*Ps)[132]  = (float(*)[132])(sm + FL_PE);
    float* rsum       = sm + FL_RS;                    // [4][128]

    const int z  = blockIdx.y;
    const int m0 = blockIdx.x * 128;

    const float* Aq = gQ + (size_t)z * LQ * DH;
    const float* Bk = gK + (size_t)z * LK * DH;
    const float* Vt = gVt + (size_t)z * DH * LK;

    const int tid  = threadIdx.x;
    const int warp = tid >> 5;
    const int lane = tid & 31;
    const int g = lane >> 2;
    const int t = lane & 3;
    const int wm    = (warp & 3) * 32;
    const int wnidx = warp >> 2;          // 0..3
    const int wn    = wnidx * 32;
    const int pv_kh = (warp >> 2) & 1;    // k half
    const int pv_ng = (warp >> 3) & 1;    // n group (32 cols)

    // ---- stage Q once (pre-rounded; pure float4 copy) ----
#pragma unroll
    for (int qq = 0; qq < 4; qq++) {
        int idx = tid + qq * 512;            // 0..2047
        int row = idx >> 4;
        int c4  = (idx & 15) << 2;
        *(float4*)&Qs[row][c4] = *(const float4*)&Aq[(size_t)(m0 + row) * DH + c4];
    }
    rsum[tid] = 0.f;

    float Oacc[2][4][4];
#pragma unroll
    for (int i = 0; i < 2; i++)
#pragma unroll
        for (int j = 0; j < 4; j++)
#pragma unroll
            for (int r = 0; r < 4; r++) Oacc[i][j][r] = 0.f;

    const float* mbase = mask + (size_t)(z >> 4) * LK;

    for (int n0 = 0; n0 < LK; n0 += 128) {
        __syncthreads();   // previous PV reads of Ps/Vs done before restaging

        const int jlo = m0 - n0 + 1920;      // in [0, 2816]; -128 per tile

        // ---- stage K tile (overwrites last tile's Vs; PV done) ----
#pragma unroll
        for (int qq = 0; qq < 4; qq++) {
            int idx = tid + qq * 512;        // 0..2047
            int row = idx >> 4;              // 0..127
            int c4  = (idx & 15) << 2;
            *(float4*)&Ks[row][c4] = *(const float4*)&Bk[(size_t)(n0 + row) * DH + c4];
        }
        // ---- stage E ring: full window first tile, 128 new rows after ----
        if (n0 == 0) {
#pragma unroll
            for (int qq = 0; qq < 8; qq++) {
                int idx = tid + qq * 512;    // 0..4095
                int row = idx >> 4;          // 0..255
                int c4  = (idx & 15) << 2;
                int j   = jlo + row;
                *(float4*)&Es[j & 255][c4] = *(const float4*)&gEr[(size_t)j * DH + c4];
            }
        } else {
#pragma unroll
            for (int qq = 0; qq < 4; qq++) {
                int idx = tid + qq * 512;    // 0..2047
                int row = idx >> 4;          // 0..127 (new low rows)
                int c4  = (idx & 15) << 2;
                int j   = jlo + row;
                *(float4*)&Es[j & 255][c4] = *(const float4*)&gEr[(size_t)j * DH + c4];
            }
        }
        __syncthreads();

        float acc[2][4][4];
#pragma unroll
        for (int i = 0; i < 2; i++)
#pragma unroll
            for (int j = 0; j < 4; j++)
#pragma unroll
                for (int r = 0; r < 4; r++) acc[i][j][r] = 0.f;

        // ---- S = Q @ K^T ----
#pragma unroll
        for (int k8 = 0; k8 < 8; k8++) {
            const int c0 = k8 * 8 + t, c1 = c0 + 4;
            uint32_t af[2][4], bf[4][2];
#pragma unroll
            for (int mt = 0; mt < 2; mt++) {
                int r0 = wm + mt * 16 + g;
                af[mt][0] = __float_as_uint(Qs[r0][c0]);
                af[mt][1] = __float_as_uint(Qs[r0 + 8][c0]);
                af[mt][2] = __float_as_uint(Qs[r0][c1]);
                af[mt][3] = __float_as_uint(Qs[r0 + 8][c1]);
            }
#pragma unroll
            for (int nt = 0; nt < 4; nt++) {
                int nr = wn + nt * 8 + g;
                bf[nt][0] = __float_as_uint(Ks[nr][c0]);
                bf[nt][1] = __float_as_uint(Ks[nr][c1]);
            }
#pragma unroll
            for (int mt = 0; mt < 2; mt++)
#pragma unroll
                for (int nt = 0; nt < 4; nt++)
                    mma_tf32(acc[mt][nt], af[mt], bf[nt]);
        }

        // ---- banded positional passes (src 0 = Q-side, src 1 = K-side) ----
#pragma unroll 1
        for (int src = 0; src < 2; src++) {
            const float (*Src)[68] = (src == 0) ? Qs : Ks;
            const int ebase  = (src == 0) ? wm : (96 - wm);
            const int estart = jlo + ebase + wnidx * 40;   // ABSOLUTE e start

            float pacc[2][5][4];
#pragma unroll
            for (int i = 0; i < 2; i++)
#pragma unroll
                for (int j = 0; j < 5; j++)
#pragma unroll
                    for (int r = 0; r < 4; r++) pacc[i][j][r] = 0.f;

#pragma unroll
            for (int k8 = 0; k8 < 8; k8++) {
                const int c0 = k8 * 8 + t, c1 = c0 + 4;
                uint32_t af[2][4], bf[5][2];
#pragma unroll
                for (int mt = 0; mt < 2; mt++) {
                    int r0 = wm + mt * 16 + g;
                    af[mt][0] = __float_as_uint(Src[r0][c0]);
                    af[mt][1] = __float_as_uint(Src[r0 + 8][c0]);
                    af[mt][2] = __float_as_uint(Src[r0][c1]);
                    af[mt][3] = __float_as_uint(Src[r0 + 8][c1]);
                }
#pragma unroll
                for (int nt = 0; nt < 5; nt++) {
                    int er = (estart + nt * 8 + g) & 255;  // ring slot
                    bf[nt][0] = __float_as_uint(Es[er][c0]);
                    bf[nt][1] = __float_as_uint(Es[er][c1]);
                }
#pragma unroll
                for (int mt = 0; mt < 2; mt++)
#pragma unroll
                    for (int nt = 0; nt < 5; nt++)
                        mma_tf32(pacc[mt][nt], af[mt], bf[nt]);
            }

            // store band fragment (float2)
#pragma unroll
            for (int mt = 0; mt < 2; mt++)
#pragma unroll
                for (int half = 0; half < 2; half++) {
                    int r = wm + mt * 16 + g + half * 8;
#pragma unroll
                    for (int nt = 0; nt < 5; nt++) {
                        float2 v2;
                        v2.x = pacc[mt][nt][half * 2 + 0];
                        v2.y = pacc[mt][nt][half * 2 + 1];
                        *(float2*)&PE[r][wnidx * 40 + nt * 8 + t * 2] = v2;
                    }
                }
            __syncthreads();

            // predicate-free diagonal gather
#pragma unroll
            for (int mt = 0; mt < 2; mt++)
#pragma unroll
                for (int half = 0; half < 2; half++) {
                    const int i = wm + mt * 16 + g + half * 8;
#pragma unroll
                    for (int nt = 0; nt < 4; nt++)
#pragma unroll
                        for (int cc = 0; cc < 2; cc++) {
                            const int jj = wn + nt * 8 + t * 2 + cc;
                            if (src == 0)
                                acc[mt][nt][half * 2 + cc] += PE[i][(i & 31) + 127 - jj];
                            else
                                acc[mt][nt][half * 2 + cc] += PE[jj][i - (jj & 31) + 31];
                        }
                }
            __syncthreads();
        }

        // ---- exp + row sums + stash P (tf32) into Ps ----
        {
            float rpart[4] = {0.f, 0.f, 0.f, 0.f};
#pragma unroll
            for (int mt = 0; mt < 2; mt++)
#pragma unroll
                for (int half = 0; half < 2; half++) {
                    const int r = wm + mt * 16 + g + half * 8;
#pragma unroll
                    for (int nt = 0; nt < 4; nt++) {
                        const int nloc = wn + nt * 8 + t * 2;
                        float p0 = __expf(acc[mt][nt][half * 2 + 0] * 0.125f
                                          + mbase[n0 + nloc]);
                        float p1 = __expf(acc[mt][nt][half * 2 + 1] * 0.125f
                                          + mbase[n0 + nloc + 1]);
                        rpart[mt * 2 + half] += p0 + p1;
                        float2 v2; v2.x = tf32r(p0); v2.y = tf32r(p1);
                        *(float2*)&Ps[r][nloc] = v2;
                    }
                }
#pragma unroll
            for (int i = 0; i < 4; i++) {
                rpart[i] += __shfl_xor_sync(0xffffffffu, rpart[i], 1);
                rpart[i] += __shfl_xor_sync(0xffffffffu, rpart[i], 2);
            }
            if (t == 0) {
#pragma unroll
                for (int i = 0; i < 4; i++) {
                    const int r = wm + (i >> 1) * 16 + g + (i & 1) * 8;
                    rsum[wnidx * 128 + r] += rpart[i];
                }
            }
        }

        // ---- stage V tile into Ks region (K reads all done) ----
#pragma unroll
        for (int qq = 0; qq < 4; qq++) {
            int idx = tid + qq * 512;        // 0..2047 float4 slots
            int row = idx >> 5;              // 0..63 (dh)
            int c4  = (idx & 31) << 2;       // 0..124
            *(float4*)&Vs[row][c4] = *(const float4*)&Vt[(size_t)row * LK + n0 + c4];
        }
        __syncthreads();

        // ---- O += P @ V^T  (warps: 4m x 2n x 2k-split) ----
#pragma unroll
        for (int k8 = 0; k8 < 8; k8++) {
            const int c0 = pv_kh * 64 + k8 * 8 + t, c1 = c0 + 4;
            uint32_t af[2][4], bf[4][2];
#pragma unroll
            for (int mt = 0; mt < 2; mt++) {
                int r0 = wm + mt * 16 + g;
                af[mt][0] = __float_as_uint(Ps[r0][c0]);
                af[mt][1] = __float_as_uint(Ps[r0 + 8][c0]);
                af[mt][2] = __float_as_uint(Ps[r0][c1]);
                af[mt][3] = __float_as_uint(Ps[r0 + 8][c1]);
            }
#pragma unroll
            for (int nt = 0; nt < 4; nt++) {
                int nr = pv_ng * 32 + nt * 8 + g;
                bf[nt][0] = __float_as_uint(Vs[nr][c0]);
                bf[nt][1] = __float_as_uint(Vs[nr][c1]);
            }
#pragma unroll
            for (int mt = 0; mt < 2; mt++)
#pragma unroll
                for (int nt = 0; nt < 4; nt++)
                    mma_tf32(Oacc[mt][nt], af[mt], bf[nt]);
        }
    }

    // ---- epilogue: combine k-split halves, normalize, write out ----
    __syncthreads();
    if (tid < 128) {
        float s = rsum[tid] + rsum[128 + tid] + rsum[256 + tid] + rsum[384 + tid];
        rsum[tid] = 1.0f / s;
    }
    if (pv_kh == 1) {
#pragma unroll
        for (int mt = 0; mt < 2; mt++)
#pragma unroll
            for (int half = 0; half < 2; half++) {
                const int r = wm + mt * 16 + g + half * 8;
#pragma unroll
                for (int nt = 0; nt < 4; nt++) {
                    float2 v2;
                    v2.x = Oacc[mt][nt][half * 2 + 0];
                    v2.y = Oacc[mt][nt][half * 2 + 1];
                    *(float2*)&Ocmb[r][pv_ng * 32 + nt * 8 + t * 2] = v2;
                }
            }
    }
    __syncthreads();
    if (pv_kh == 0) {
        const int b = z >> 4, h = z & 15;
#pragma unroll
        for (int mt = 0; mt < 2; mt++)
#pragma unroll
            for (int half = 0; half < 2; half++) {
                const int r = wm + mt * 16 + g + half * 8;
                const float inv = rsum[r];
#pragma unroll
                for (int nt = 0; nt < 4; nt++) {
                    const int ncol = pv_ng * 32 + nt * 8 + t * 2;
                    float2 o;
                    o.x = (Oacc[mt][nt][half * 2 + 0] + Ocmb[r][ncol + 0]) * inv;
                    o.y = (Oacc[mt][nt][half * 2 + 1] + Ocmb[r][ncol + 1]) * inv;
                    *(float2*)&out[((size_t)b * LQ + m0 + r) * DMODEL + h * DH + ncol] = o;
                }
            }
    }
}

// ---------------- host ----------------
extern "C" void kernel_launch(void* const* d_in, const int* in_sizes, int n_in,
                              void* d_out, int out_size)
{
    (void)in_sizes; (void)n_in; (void)out_size;
    const float* hid  = (const float*)d_in[0];   // [4,2048,1024]
    const float* qhid = (const float*)d_in[1];   // [4,1024,1024]
    const float* mask = (const float*)d_in[2];   // [4,1,1,2048]
    const float* Wq   = (const float*)d_in[3];
    const float* bq   = (const float*)d_in[4];
    const float* Wk   = (const float*)d_in[5];
    const float* bk   = (const float*)d_in[6];
    const float* Wv   = (const float*)d_in[7];
    const float* bv   = (const float*)d_in[8];
    const float* emb  = (const float*)d_in[9];   // [4095,64]
    float* out = (float*)d_out;                  // [4,1024,1024]

    static bool attr_set = false;
    if (!attr_set) {
        cudaFuncSetAttribute(flash_tc,
                             cudaFuncAttributeMaxDynamicSharedMemorySize,
                             FL_SMEM_BYTES);
        cudaFuncSetAttribute(proj_all,
                             cudaFuncAttributeMaxDynamicSharedMemorySize,
                             PR_SMEM_BYTES);
        attr_set = true;
    }

    proj_all<<<768, 512, PR_SMEM_BYTES>>>(hid, qhid, Wq, bq, Wk, bk, Wv, bv, emb);

    flash_tc<<<dim3(LQ / 128, ZTOT), 512, FL_SMEM_BYTES>>>(mask, out);
}